// round 14
// baseline (speedup 1.0000x reference)
#include <cuda_runtime.h>
#include <cstdint>
#include <math.h>

#define FDIM 1024

// -------- packed tf32 weight scratch (filled by k_prep each launch) --------
static __device__ __align__(16) float2 g_W1p[163840];   // br0-4 fc1: [it32][ks4][c320][t4]
static __device__ __align__(16) float2 g_W2p[163840];   // br0-4 fc2: [p20][ks8][c256][t4]
static __device__ __align__(16) float2 g_W1p5[32768];   // br5 fc1:  [it32][ks4][c64][t4]
static __device__ __align__(16) float2 g_W2p5[32768];   // br5 fc2:  [fc8][ks8][c128][t4]

// ---------------- helpers ----------------
__device__ __forceinline__ uint32_t f2t(float f) {
    uint32_t r;
    asm("cvt.rna.tf32.f32 %0, %1;" : "=r"(r) : "f"(f));
    return r;
}
__device__ __forceinline__ void mma8(float* c, uint32_t a0, uint32_t a1, uint32_t a2, uint32_t a3,
                                     uint32_t b0, uint32_t b1) {
    asm volatile(
        "mma.sync.aligned.m16n8k8.row.col.f32.tf32.tf32.f32 "
        "{%0,%1,%2,%3},{%4,%5,%6,%7},{%8,%9},{%0,%1,%2,%3};"
        : "+f"(c[0]), "+f"(c[1]), "+f"(c[2]), "+f"(c[3])
        : "r"(a0), "r"(a1), "r"(a2), "r"(a3), "r"(b0), "r"(b1));
}
__device__ __forceinline__ uint32_t saddr(const void* p) {
    return (uint32_t)__cvta_generic_to_shared(p);
}
__device__ __forceinline__ void cp16(uint32_t s, const void* g) {
    asm volatile("cp.async.ca.shared.global [%0], [%1], 16;" :: "r"(s), "l"(g));
}
__device__ __forceinline__ void cp_commit() { asm volatile("cp.async.commit_group;"); }
__device__ __forceinline__ void cp_wait0() { asm volatile("cp.async.wait_group 0;"); }
__device__ __forceinline__ void cp_wait1() { asm volatile("cp.async.wait_group 1;"); }

__device__ __forceinline__ float softplus_f(float v) {
    return fmaxf(v, 0.f) + log1pf(__expf(-fabsf(v)));
}
__device__ __forceinline__ float sigmoid_f(float v) {
    return 1.f / (1.f + __expf(-v));
}

// =====================================================================
// k_prep: repack W1/W2 into tf32 float2-pair smem-image layouts.
// pair(ks,c,t) = ( tf32(W[kbase+ks*8+t][c]), tf32(W[kbase+ks*8+t+4][c]) )
// =====================================================================
__global__ void __launch_bounds__(256)
k_prep(const float* __restrict__ W1, const float* __restrict__ W2) {
    int i = blockIdx.x * 256 + threadIdx.x;
    if (i < 163840) {                       // W1 branches 0..4
        int t = i & 3; int r = i >> 2;
        int c = r % 320; int r2 = r / 320;
        int ks = r2 & 3; int it = r2 >> 2;
        int m = c >> 6, h = c & 63;
        int k = it * 32 + ks * 8 + t;
        float lo = W1[((long)m * 1024 + k) * 64 + h];
        float hi = W1[((long)m * 1024 + k + 4) * 64 + h];
        g_W1p[i] = make_float2(__uint_as_float(f2t(lo)), __uint_as_float(f2t(hi)));
    } else if (i < 327680) {                // W2 branches 0..4
        int j = i - 163840;
        int t = j & 3; int r = j >> 2;
        int c = r % 256; int r2 = r / 256;
        int ks = r2 & 7; int p = r2 >> 3;   // p = fc*5 + m
        int m = p % 5, fc = p / 5;
        int k = ks * 8 + t;
        int gc = fc * 256 + c;
        float lo = W2[((long)(m * 64 + k)) * 1024 + gc];
        float hi = W2[((long)(m * 64 + k + 4)) * 1024 + gc];
        g_W2p[j] = make_float2(__uint_as_float(f2t(lo)), __uint_as_float(f2t(hi)));
    } else if (i < 360448) {                // W1 branch 5
        int j = i - 327680;
        int t = j & 3; int r = j >> 2;
        int c = r & 63; int r2 = r >> 6;
        int ks = r2 & 3; int it = r2 >> 2;
        int k = it * 32 + ks * 8 + t;
        float lo = W1[(5l * 1024 + k) * 64 + c];
        float hi = W1[(5l * 1024 + k + 4) * 64 + c];
        g_W1p5[j] = make_float2(__uint_as_float(f2t(lo)), __uint_as_float(f2t(hi)));
    } else if (i < 393216) {                // W2 branch 5
        int j = i - 360448;
        int t = j & 3; int r = j >> 2;
        int c = r & 127; int r2 = r >> 7;
        int ks = r2 & 7; int fc = r2 >> 3;
        int k = ks * 8 + t;
        int gc = fc * 128 + c;
        float lo = W2[((long)(5 * 64 + k)) * 1024 + gc];
        float hi = W2[((long)(5 * 64 + k + 4)) * 1024 + gc];
        g_W2p5[j] = make_float2(__uint_as_float(f2t(lo)), __uint_as_float(f2t(hi)));
    }
}

// =====================================================================
// k_mlp: ONE branch (m = bid%5) over a 128-token tile (tile = bid/5).
//  256 threads, 2 CTA/SM, 100KB smem.
//  Phase 1 (8 warps, 16 rows each, full 64 cols): sH[128,64] = relu(x@W1[m]+B1)
//  Phase 2: 8 chunks of 128 feats; each W2 chunk consumed by TWO 64-row
//           halves sequentially (2x weight reuse per smem fill).
//  smem: sH 128x68 = 8704 fl | pb region 16384 fl
//        phase1 stage (6656): x 128x36 (4608) + W1p (2048); 2 stages = 13312
//        phase2 stage 8192; 2 stages = 16384
// =====================================================================
#define MLP_SH 68
#define MLP_SMEM ((8704 + 16384) * 4)   // 100352 B

__global__ void __launch_bounds__(256, 2)
k_mlp(const float* __restrict__ x, const float* __restrict__ B1,
      const float* __restrict__ B2, float* __restrict__ out, int N) {
    extern __shared__ float sm[];
    float* sH = sm;
    float* pb = sm + 8704;

    int bid = blockIdx.x;
    int m = bid % 5;
    long rowBase = (long)(bid / 5) * 128;

    int tid = threadIdx.x;
    int lane = tid & 31, warp = tid >> 5;
    int g = lane >> 2, t = lane & 3;
    const float* xb = x + rowBase * FDIM;

    // ---------------- phase 1: sH[128,64] = relu(x @ W1[m] + B1) ----------------
    float acc[32];
#pragma unroll
    for (int i = 0; i < 32; i++) acc[i] = 0.f;

    auto issue1 = [&](int it, int s) {
        float* sx = pb + s * 6656;
        float* swp = sx + 4608;
        int k0 = it * 32;
#pragma unroll
        for (int j = 0; j < 4; j++) {      // x tile: 1024 granules, 4/thread
            int idx = j * 256 + tid;
            int r = idx >> 3, seg = idx & 7;
            cp16(saddr(sx + r * 36 + seg * 4), xb + (long)r * FDIM + k0 + seg * 4);
        }
#pragma unroll
        for (int j = 0; j < 2; j++) {      // W1p chunk: 512 granules, 2/thread
            int idx = j * 256 + tid;
            int ks = idx >> 7, within = idx & 127;
            const float* src = (const float*)(g_W1p + (long)(it * 4 + ks) * 1280 + m * 256);
            cp16(saddr(swp + ks * 512 + within * 4), src + within * 4);
        }
        cp_commit();
    };

    issue1(0, 0);
    for (int it = 0; it < 32; ++it) {
        int s = it & 1;
        if (it + 1 < 32) { issue1(it + 1, s ^ 1); cp_wait1(); }
        else             { cp_wait0(); }
        __syncthreads();
        const float* sx = pb + s * 6656;
        const float2* wb = (const float2*)(sx + 4608);
        const float* ax = sx + (warp * 16 + g) * 36;
#pragma unroll
        for (int ks = 0; ks < 4; ks++) {
            int kb = ks * 8;
            uint32_t a0 = f2t(ax[kb + t]);
            uint32_t a1 = f2t(ax[8 * 36 + kb + t]);
            uint32_t a2 = f2t(ax[kb + t + 4]);
            uint32_t a3 = f2t(ax[8 * 36 + kb + t + 4]);
#pragma unroll
            for (int nt = 0; nt < 8; nt++) {
                int c = nt * 8 + g;
                float2 bb = wb[(ks * 64 + c) * 4 + t];
                mma8(acc + nt * 4, a0, a1, a2, a3,
                     __float_as_uint(bb.x), __float_as_uint(bb.y));
            }
        }
        __syncthreads();
    }

    // prefetch phase-2 chunk 0 (phase-1 buffers dead past trailing barrier)
    {
#pragma unroll
        for (int j = 0; j < 8; j++) {      // 2048 granules, 8/thread
            int idx = j * 256 + tid;
            int ks = idx >> 8, within = idx & 255;
            const float* src = (const float*)(g_W2p + (long)m * 8192 + ks * 1024);
            cp16(saddr(pb + ks * 1024 + within * 4), src + within * 4);
        }
        cp_commit();
    }

    // H -> smem (relu + bias, tf32 bits), pitch 68
    {
        int rl = warp * 16 + g;
#pragma unroll
        for (int nt = 0; nt < 8; nt++) {
            int col = nt * 8 + 2 * t;
            float bb0 = B1[m * 64 + col], bb1 = B1[m * 64 + col + 1];
            float2 v;
            v.x = __uint_as_float(f2t(fmaxf(acc[nt * 4 + 0] + bb0, 0.f)));
            v.y = __uint_as_float(f2t(fmaxf(acc[nt * 4 + 1] + bb1, 0.f)));
            *(float2*)(sH + rl * MLP_SH + col) = v;
            v.x = __uint_as_float(f2t(fmaxf(acc[nt * 4 + 2] + bb0, 0.f)));
            v.y = __uint_as_float(f2t(fmaxf(acc[nt * 4 + 3] + bb1, 0.f)));
            *(float2*)(sH + (rl + 8) * MLP_SH + col) = v;
        }
    }

    // ---------------- phase 2: out[128,1024] in 8 chunks of 128 feats ----------------
    int wm2 = warp >> 2, wn2 = warp & 3;   // 2M x 4N over each 64-row half

    auto issue2 = [&](int jc, int s) {
        float* sw = pb + s * 8192;
        int fcb = jc >> 1, half = jc & 1;
        long base = (long)(fcb * 5 + m) * 8192 + half * 512;
#pragma unroll
        for (int j = 0; j < 8; j++) {      // 2048 granules, 8/thread
            int idx = j * 256 + tid;
            int ks = idx >> 8, within = idx & 255;
            const float* src = (const float*)(g_W2p + base + ks * 1024);
            cp16(saddr(sw + ks * 1024 + within * 4), src + within * 4);
        }
        cp_commit();
    };

    for (int jc = 0; jc < 8; ++jc) {
        int s = jc & 1;
        if (jc + 1 < 8) { issue2(jc + 1, s ^ 1); cp_wait1(); }
        else            { cp_wait0(); }
        __syncthreads();
        const float2* wb = (const float2*)(pb + s * 8192);

#pragma unroll 1
        for (int h = 0; h < 2; ++h) {      // two 64-row halves reuse this chunk
            int rloc = h * 64 + wm2 * 32;

            // prefetch this half's x residuals (hidden by MMAs)
            float2 xv[2][4][2];
#pragma unroll
            for (int mt = 0; mt < 2; mt++) {
                long r0 = rowBase + rloc + mt * 16 + g;
#pragma unroll
                for (int nt = 0; nt < 4; nt++) {
                    int col = jc * 128 + wn2 * 32 + nt * 8 + 2 * t;
                    xv[mt][nt][0] = *(const float2*)(x + r0 * FDIM + col);
                    xv[mt][nt][1] = *(const float2*)(x + (r0 + 8) * FDIM + col);
                }
            }

            float a2c[2][4][4];
#pragma unroll
            for (int a = 0; a < 2; a++)
#pragma unroll
                for (int b = 0; b < 4; b++)
#pragma unroll
                    for (int c = 0; c < 4; c++) a2c[a][b][c] = 0.f;

#pragma unroll
            for (int ks = 0; ks < 8; ks++) {
                uint32_t af[2][4];
#pragma unroll
                for (int mt = 0; mt < 2; mt++) {
                    const float* ap = sH + (rloc + mt * 16 + g) * MLP_SH + ks * 8 + t;
                    af[mt][0] = __float_as_uint(ap[0]);
                    af[mt][1] = __float_as_uint(ap[8 * MLP_SH]);
                    af[mt][2] = __float_as_uint(ap[4]);
                    af[mt][3] = __float_as_uint(ap[8 * MLP_SH + 4]);
                }
#pragma unroll
                for (int nt = 0; nt < 4; nt++) {
                    int c = wn2 * 32 + nt * 8 + g;
                    float2 bb = wb[(ks * 128 + c) * 4 + t];
                    uint32_t b0 = __float_as_uint(bb.x), b1 = __float_as_uint(bb.y);
                    mma8(a2c[0][nt], af[0][0], af[0][1], af[0][2], af[0][3], b0, b1);
                    mma8(a2c[1][nt], af[1][0], af[1][1], af[1][2], af[1][3], b0, b1);
                }
            }

#pragma unroll
            for (int mt = 0; mt < 2; mt++) {
                long r0 = rowBase + rloc + mt * 16 + g;
#pragma unroll
                for (int nt = 0; nt < 4; nt++) {
                    int col = jc * 128 + wn2 * 32 + nt * 8 + 2 * t;
                    float bb0 = B2[m * FDIM + col], bb1 = B2[m * FDIM + col + 1];
                    float v0 = a2c[mt][nt][0] + xv[mt][nt][0].x + bb0;
                    float v1 = a2c[mt][nt][1] + xv[mt][nt][0].y + bb1;
                    float v2 = a2c[mt][nt][2] + xv[mt][nt][1].x + bb0;
                    float v3 = a2c[mt][nt][3] + xv[mt][nt][1].y + bb1;
                    if (m == 3) {
                        v0 = softplus_f(v0); v1 = softplus_f(v1);
                        v2 = softplus_f(v2); v3 = softplus_f(v3);
                    } else if (m == 4) {
                        v0 = sigmoid_f(v0); v1 = sigmoid_f(v1);
                        v2 = sigmoid_f(v2); v3 = sigmoid_f(v3);
                    }
                    float2 o;
                    o.x = v0; o.y = v1;
                    *(float2*)(out + ((long)m * N + r0) * FDIM + col) = o;
                    o.x = v2; o.y = v3;
                    *(float2*)(out + ((long)m * N + r0 + 8) * FDIM + col) = o;
                }
            }
        }
        __syncthreads();
    }
}

// =====================================================================
// k_mlp5: branch 5 (memory MLP), 128-token tile. A = q (out slot 2),
// epilogue adds x + q. Same structure as k_mlp.
// =====================================================================
__global__ void __launch_bounds__(256, 2)
k_mlp5(const float* __restrict__ x, const float* __restrict__ B1,
       const float* __restrict__ B2, float* __restrict__ out, int N) {
    extern __shared__ float sm[];
    float* sH = sm;
    float* pb = sm + 8704;
    const float* q = out + 2ll * N * FDIM;

    long rowBase = (long)blockIdx.x * 128;
    int tid = threadIdx.x;
    int lane = tid & 31, warp = tid >> 5;
    int g = lane >> 2, t = lane & 3;
    const float* qb = q + rowBase * FDIM;

    // ---------------- phase 1 ----------------
    float acc[32];
#pragma unroll
    for (int i = 0; i < 32; i++) acc[i] = 0.f;

    auto issue1 = [&](int it, int s) {
        float* sx = pb + s * 6656;
        float* swp = sx + 4608;
        int k0 = it * 32;
#pragma unroll
        for (int j = 0; j < 4; j++) {
            int idx = j * 256 + tid;
            int r = idx >> 3, seg = idx & 7;
            cp16(saddr(sx + r * 36 + seg * 4), qb + (long)r * FDIM + k0 + seg * 4);
        }
        const float* src = (const float*)(g_W1p5 + (long)it * 1024);
#pragma unroll
        for (int j = 0; j < 2; j++) {
            int idx = j * 256 + tid;
            cp16(saddr(swp + idx * 4), src + idx * 4);
        }
        cp_commit();
    };

    issue1(0, 0);
    for (int it = 0; it < 32; ++it) {
        int s = it & 1;
        if (it + 1 < 32) { issue1(it + 1, s ^ 1); cp_wait1(); }
        else             { cp_wait0(); }
        __syncthreads();
        const float* sx = pb + s * 6656;
        const float2* wb = (const float2*)(sx + 4608);
        const float* ax = sx + (warp * 16 + g) * 36;
#pragma unroll
        for (int ks = 0; ks < 4; ks++) {
            int kb = ks * 8;
            uint32_t a0 = f2t(ax[kb + t]);
            uint32_t a1 = f2t(ax[8 * 36 + kb + t]);
            uint32_t a2 = f2t(ax[kb + t + 4]);
            uint32_t a3 = f2t(ax[8 * 36 + kb + t + 4]);
#pragma unroll
            for (int nt = 0; nt < 8; nt++) {
                int c = nt * 8 + g;
                float2 bb = wb[(ks * 64 + c) * 4 + t];
                mma8(acc + nt * 4, a0, a1, a2, a3,
                     __float_as_uint(bb.x), __float_as_uint(bb.y));
            }
        }
        __syncthreads();
    }

    // prefetch phase-2 chunk 0
    {
        const float* src = (const float*)g_W2p5;
#pragma unroll
        for (int j = 0; j < 8; j++) {
            int idx = j * 256 + tid;
            cp16(saddr(pb + idx * 4), src + idx * 4);
        }
        cp_commit();
    }

    // H5 -> smem
    {
        int rl = warp * 16 + g;
#pragma unroll
        for (int nt = 0; nt < 8; nt++) {
            int col = nt * 8 + 2 * t;
            float bb0 = B1[320 + col], bb1 = B1[320 + col + 1];
            float2 v;
            v.x = __uint_as_float(f2t(fmaxf(acc[nt * 4 + 0] + bb0, 0.f)));
            v.y = __uint_as_float(f2t(fmaxf(acc[nt * 4 + 1] + bb1, 0.f)));
            *(float2*)(sH + rl * MLP_SH + col) = v;
            v.x = __uint_as_float(f2t(fmaxf(acc[nt * 4 + 2] + bb0, 0.f)));
            v.y = __uint_as_float(f2t(fmaxf(acc[nt * 4 + 3] + bb1, 0.f)));
            *(float2*)(sH + (rl + 8) * MLP_SH + col) = v;
        }
    }

    // ---------------- phase 2 ----------------
    int wm2 = warp >> 2, wn2 = warp & 3;

    auto issue2 = [&](int jc, int s) {
        float* sw = pb + s * 8192;
        const float* src = (const float*)(g_W2p5 + (long)jc * 4096);
#pragma unroll
        for (int j = 0; j < 8; j++) {
            int idx = j * 256 + tid;
            cp16(saddr(sw + idx * 4), src + idx * 4);
        }
        cp_commit();
    };

    for (int jc = 0; jc < 8; ++jc) {
        int s = jc & 1;
        if (jc + 1 < 8) { issue2(jc + 1, s ^ 1); cp_wait1(); }
        else            { cp_wait0(); }
        __syncthreads();
        const float2* wb = (const float2*)(pb + s * 8192);

#pragma unroll 1
        for (int h = 0; h < 2; ++h) {
            int rloc = h * 64 + wm2 * 32;

            float2 xv[2][4][2];
#pragma unroll
            for (int mt = 0; mt < 2; mt++) {
                long r0 = rowBase + rloc + mt * 16 + g;
#pragma unroll
                for (int nt = 0; nt < 4; nt++) {
                    int col = jc * 128 + wn2 * 32 + nt * 8 + 2 * t;
                    float2 a0 = *(const float2*)(x + r0 * FDIM + col);
                    float2 b0 = *(const float2*)(q + r0 * FDIM + col);
                    float2 a1 = *(const float2*)(x + (r0 + 8) * FDIM + col);
                    float2 b1 = *(const float2*)(q + (r0 + 8) * FDIM + col);
                    xv[mt][nt][0] = make_float2(a0.x + b0.x, a0.y + b0.y);
                    xv[mt][nt][1] = make_float2(a1.x + b1.x, a1.y + b1.y);
                }
            }

            float a2c[2][4][4];
#pragma unroll
            for (int a = 0; a < 2; a++)
#pragma unroll
                for (int b = 0; b < 4; b++)
#pragma unroll
                    for (int c = 0; c < 4; c++) a2c[a][b][c] = 0.f;

#pragma unroll
            for (int ks = 0; ks < 8; ks++) {
                uint32_t af[2][4];
#pragma unroll
                for (int mt = 0; mt < 2; mt++) {
                    const float* ap = sH + (rloc + mt * 16 + g) * MLP_SH + ks * 8 + t;
                    af[mt][0] = __float_as_uint(ap[0]);
                    af[mt][1] = __float_as_uint(ap[8 * MLP_SH]);
                    af[mt][2] = __float_as_uint(ap[4]);
                    af[mt][3] = __float_as_uint(ap[8 * MLP_SH + 4]);
                }
#pragma unroll
                for (int nt = 0; nt < 4; nt++) {
                    int c = wn2 * 32 + nt * 8 + g;
                    float2 bb = wb[(ks * 128 + c) * 4 + t];
                    uint32_t b0 = __float_as_uint(bb.x), b1 = __float_as_uint(bb.y);
                    mma8(a2c[0][nt], af[0][0], af[0][1], af[0][2], af[0][3], b0, b1);
                    mma8(a2c[1][nt], af[1][0], af[1][1], af[1][2], af[1][3], b0, b1);
                }
            }

#pragma unroll
            for (int mt = 0; mt < 2; mt++) {
                long r0 = rowBase + rloc + mt * 16 + g;
#pragma unroll
                for (int nt = 0; nt < 4; nt++) {
                    int col = jc * 128 + wn2 * 32 + nt * 8 + 2 * t;
                    float bb0 = B2[5 * FDIM + col], bb1 = B2[5 * FDIM + col + 1];
                    float2 o;
                    o.x = a2c[mt][nt][0] + xv[mt][nt][0].x + bb0;
                    o.y = a2c[mt][nt][1] + xv[mt][nt][0].y + bb1;
                    *(float2*)(out + (5ll * N + r0) * FDIM + col) = o;
                    o.x = a2c[mt][nt][2] + xv[mt][nt][1].x + bb0;
                    o.y = a2c[mt][nt][3] + xv[mt][nt][1].y + bb1;
                    *(float2*)(out + (5ll * N + r0 + 8) * FDIM + col) = o;
                }
            }
        }
        __syncthreads();
    }
}

// =====================================================================
extern "C" void kernel_launch(void* const* d_in, const int* in_sizes, int n_in,
                              void* d_out, int out_size) {
    const float* x  = (const float*)d_in[0];
    const float* W1 = (const float*)d_in[1];
    const float* B1 = (const float*)d_in[2];
    const float* W2 = (const float*)d_in[3];
    const float* B2 = (const float*)d_in[4];
    float* out = (float*)d_out;
    int N = in_sizes[0] / FDIM;

    cudaFuncSetAttribute(k_mlp,  cudaFuncAttributeMaxDynamicSharedMemorySize, MLP_SMEM);
    cudaFuncSetAttribute(k_mlp5, cudaFuncAttributeMaxDynamicSharedMemorySize, MLP_SMEM);

    k_prep<<<1536, 256>>>(W1, W2);
    k_mlp<<<(N / 128) * 5, 256, MLP_SMEM>>>(x, B1, B2, out, N);
    k_mlp5<<<N / 128, 256, MLP_SMEM>>>(x, B1, B2, out, N);
}

// round 17
// speedup vs baseline: 1.3438x; 1.3438x over previous
#include <cuda_runtime.h>
#include <cuda_fp16.h>
#include <cstdint>
#include <math.h>

#define FDIM 1024

// -------- fp16 packed scratch (filled by k_xh/k_prep each launch) --------
static __device__ __align__(16) uint2 g_W1ph[81920];    // br0-4 fc1: [blk64][c320][t4]
static __device__ __align__(16) uint2 g_W2ph[81920];    // br0-4 fc2: [p20][ks4][c256][t4]
static __device__ __align__(16) uint2 g_W1p5h[16384];   // br5 fc1:  [blk64][c64][t4]
static __device__ __align__(16) uint2 g_W2p5h[16384];   // br5 fc2:  [jc8][ks4][c128][t4]
static __device__ __align__(16) uint32_t g_xh[16777216]; // x fp16 row-major [32768][512 u32]
static __device__ __align__(16) uint32_t g_qh[16777216]; // q fp16 row-major (by k_mlp m==2)

// ---------------- helpers ----------------
__device__ __forceinline__ uint32_t h2pack(float a, float b) {
    __half2 h = __floats2half2_rn(a, b);
    return *reinterpret_cast<uint32_t*>(&h);
}
__device__ __forceinline__ void mma16(float* c, uint32_t a0, uint32_t a1, uint32_t a2, uint32_t a3,
                                      uint32_t b0, uint32_t b1) {
    asm volatile(
        "mma.sync.aligned.m16n8k16.row.col.f32.f16.f16.f32 "
        "{%0,%1,%2,%3},{%4,%5,%6,%7},{%8,%9},{%0,%1,%2,%3};"
        : "+f"(c[0]), "+f"(c[1]), "+f"(c[2]), "+f"(c[3])
        : "r"(a0), "r"(a1), "r"(a2), "r"(a3), "r"(b0), "r"(b1));
}
__device__ __forceinline__ uint32_t saddr(const void* p) {
    return (uint32_t)__cvta_generic_to_shared(p);
}
__device__ __forceinline__ void cp16(uint32_t s, const void* g) {
    asm volatile("cp.async.ca.shared.global [%0], [%1], 16;" :: "r"(s), "l"(g));
}
__device__ __forceinline__ void cp_commit() { asm volatile("cp.async.commit_group;"); }
__device__ __forceinline__ void cp_wait0() { asm volatile("cp.async.wait_group 0;"); }
__device__ __forceinline__ void cp_wait1() { asm volatile("cp.async.wait_group 1;"); }
__device__ __forceinline__ void cp_wait2() { asm volatile("cp.async.wait_group 2;"); }

__device__ __forceinline__ float softplus_f(float v) {
    return fmaxf(v, 0.f) + log1pf(__expf(-fabsf(v)));
}
__device__ __forceinline__ float sigmoid_f(float v) {
    return 1.f / (1.f + __expf(-v));
}

// =====================================================================
// k_xh: x f32 -> fp16 packed image, row-major.
// =====================================================================
__global__ void __launch_bounds__(256)
k_xh(const float* __restrict__ x) {
    long i = (long)blockIdx.x * 256 + threadIdx.x;
    float2 v = *(const float2*)(x + i * 2);
    g_xh[i] = h2pack(v.x, v.y);
}

// =====================================================================
// k_prep: pack W1/W2 into fp16-pair smem-image layouts.
// For each K16 block at k0: uint2{ pack(W[k0+2t],W[k0+2t+1]),
//                                  pack(W[k0+2t+8],W[k0+2t+9]) } at col c.
// =====================================================================
__global__ void __launch_bounds__(256)
k_prep(const float* __restrict__ W1, const float* __restrict__ W2) {
    int i = blockIdx.x * 256 + threadIdx.x;
    if (i < 81920) {                        // W1 branches 0..4: [blk64][c320][t4]
        int t = i & 3; int r = i >> 2;
        int c = r % 320; int blk = r / 320;
        int m = c >> 6, h = c & 63;
        int k0 = blk * 16;
        const float* base = W1 + (long)m * 1024 * 64 + h;
        uint2 o;
        o.x = h2pack(base[(k0 + 2 * t) * 64],     base[(k0 + 2 * t + 1) * 64]);
        o.y = h2pack(base[(k0 + 2 * t + 8) * 64], base[(k0 + 2 * t + 9) * 64]);
        g_W1ph[i] = o;
    } else if (i < 163840) {                // W2 branches 0..4: [p20][ks4][c256][t4]
        int j = i - 81920;
        int t = j & 3; int r = j >> 2;
        int c = r % 256; int r2 = r / 256;
        int ks = r2 & 3; int p = r2 >> 2;   // p = fc*5 + m
        int m = p % 5, fc = p / 5;
        int k0 = ks * 16;
        int gc = fc * 256 + c;
        const float* base = W2 + (long)m * 64 * 1024 + gc;
        uint2 o;
        o.x = h2pack(base[(k0 + 2 * t) * 1024],     base[(k0 + 2 * t + 1) * 1024]);
        o.y = h2pack(base[(k0 + 2 * t + 8) * 1024], base[(k0 + 2 * t + 9) * 1024]);
        g_W2ph[j] = o;
    } else if (i < 180224) {                // W1 branch 5: [blk64][c64][t4]
        int j = i - 163840;
        int t = j & 3; int r = j >> 2;
        int c = r & 63; int blk = r >> 6;
        int k0 = blk * 16;
        const float* base = W1 + 5l * 1024 * 64 + c;
        uint2 o;
        o.x = h2pack(base[(k0 + 2 * t) * 64],     base[(k0 + 2 * t + 1) * 64]);
        o.y = h2pack(base[(k0 + 2 * t + 8) * 64], base[(k0 + 2 * t + 9) * 64]);
        g_W1p5h[j] = o;
    } else if (i < 196608) {                // W2 branch 5: [jc8][ks4][c128][t4]
        int j = i - 180224;
        int t = j & 3; int r = j >> 2;
        int c = r & 127; int r2 = r >> 7;
        int ks = r2 & 3; int jc = r2 >> 2;
        int k0 = ks * 16;
        int gc = jc * 128 + c;
        const float* base = W2 + 5l * 64 * 1024 + gc;
        uint2 o;
        o.x = h2pack(base[(k0 + 2 * t) * 1024],     base[(k0 + 2 * t + 1) * 1024]);
        o.y = h2pack(base[(k0 + 2 * t + 8) * 1024], base[(k0 + 2 * t + 9) * 1024]);
        g_W2p5h[j] = o;
    }
}

// =====================================================================
// k_mlp: ONE branch (m = bid%5) over a 64-token tile (tile = bid/5).
//  256 threads, 2 CTA/SM, 60KB smem, fp16 HMMA m16n8k16.
//  Phase 1 (warps 4Mx2N): 16 iters of K=64, 3-stage cp.async ring.
//  Phase 2 (warps 2Mx4N): 8 chunks of 128 feats, K=64 in 4 MMAs.
//  m==2 epilogue additionally writes q fp16 image (g_qh) for k_mlp5.
//  smem (u32): sH 64x36=2304 | pb: phase1 3x4352=13056 / phase2 2x4096 (aliased)
// =====================================================================
#define MLP_SMEM ((2304 + 13056) * 4)   // 61440 B

__global__ void __launch_bounds__(256, 2)
k_mlp(const float* __restrict__ x, const float* __restrict__ B1,
      const float* __restrict__ B2, float* __restrict__ out, int N) {
    extern __shared__ uint32_t sm[];
    uint32_t* sH = sm;
    uint32_t* pb = sm + 2304;

    int bid = blockIdx.x;
    int m = bid % 5;
    long rowBase = (long)(bid / 5) * 64;

    int tid = threadIdx.x;
    int lane = tid & 31, warp = tid >> 5;
    int g = lane >> 2, t = lane & 3;

    // ---------------- phase 1: sH[64,64]h = relu(x @ W1[m] + B1) ----------------
    int wm = warp >> 1, wn = warp & 1;     // 4M x 2N
    float acc[16];
#pragma unroll
    for (int i = 0; i < 16; i++) acc[i] = 0.f;

    auto issue1 = [&](int it, int s) {
        uint32_t* sx = pb + s * 4352;
        uint32_t* swp = sx + 2304;
        int k0u = it * 32;                 // 64 fp16 = 32 u32 per iter
#pragma unroll
        for (int j = 0; j < 2; j++) {      // x tile: 512 granules, 2/thread
            int idx = j * 256 + tid;
            int r = idx >> 3, seg = idx & 7;
            cp16(saddr(sx + r * 36 + seg * 4),
                 g_xh + (rowBase + r) * 512 + k0u + seg * 4);
        }
#pragma unroll
        for (int j = 0; j < 2; j++) {      // W1 chunk: 512 granules, 2/thread
            int idx = j * 256 + tid;
            int ks = idx >> 7, within = idx & 127;
            cp16(saddr(swp + ks * 512 + within * 4),
                 (const uint32_t*)(g_W1ph + (long)(it * 4 + ks) * 1280 + m * 256) + within * 4);
        }
        cp_commit();
    };

    issue1(0, 0); issue1(1, 1);
    for (int it = 0; it < 16; ++it) {
        int s = it % 3;
        if (it + 2 < 16) issue1(it + 2, (it + 2) % 3);
        if (it < 14) cp_wait2(); else if (it == 14) cp_wait1(); else cp_wait0();
        __syncthreads();
        const uint32_t* sx = pb + s * 4352;
        const uint2* wb = (const uint2*)(sx + 2304);
        const uint32_t* ax = sx + (wm * 16 + g) * 36;
#pragma unroll
        for (int ks = 0; ks < 4; ks++) {
            int kb = ks * 8;
            uint32_t a0 = ax[kb + t];
            uint32_t a1 = ax[8 * 36 + kb + t];
            uint32_t a2 = ax[kb + t + 4];
            uint32_t a3 = ax[8 * 36 + kb + t + 4];
#pragma unroll
            for (int nt = 0; nt < 4; nt++) {
                int c = wn * 32 + nt * 8 + g;
                uint2 bb = wb[(ks * 64 + c) * 4 + t];
                mma16(acc + nt * 4, a0, a1, a2, a3, bb.x, bb.y);
            }
        }
        __syncthreads();
    }

    // prefetch phase-2 chunk 0 (phase-1 buffers dead past trailing barrier)
    {
        const uint32_t* base = (const uint32_t*)g_W2ph + (long)m * 8192;
#pragma unroll
        for (int j = 0; j < 4; j++) {      // 1024 granules, 4/thread
            int idx = j * 256 + tid;
            int ks = idx >> 8, within = idx & 255;
            cp16(saddr(pb + ks * 1024 + within * 4), base + ks * 2048 + within * 4);
        }
        cp_commit();
    }

    // H -> smem fp16 (relu + bias), pitch 36 u32
    {
        int rl = wm * 16 + g;
#pragma unroll
        for (int nt = 0; nt < 4; nt++) {
            int colh = wn * 32 + nt * 8 + 2 * t;
            float bb0 = B1[m * 64 + colh], bb1 = B1[m * 64 + colh + 1];
            int cu = wn * 16 + nt * 4 + t;
            sH[rl * 36 + cu] = h2pack(fmaxf(acc[nt * 4 + 0] + bb0, 0.f),
                                      fmaxf(acc[nt * 4 + 1] + bb1, 0.f));
            sH[(rl + 8) * 36 + cu] = h2pack(fmaxf(acc[nt * 4 + 2] + bb0, 0.f),
                                            fmaxf(acc[nt * 4 + 3] + bb1, 0.f));
        }
    }

    // ---------------- phase 2: out[64,1024] in 8 chunks of 128 feats ----------------
    int wm2 = warp >> 2, wn2 = warp & 3;   // 2M x 4N, warp tile 32x32

    auto issue2 = [&](int jc, int s) {
        uint32_t* sw = pb + s * 4096;
        int fcb = jc >> 1, half = jc & 1;
        const uint32_t* base = (const uint32_t*)g_W2ph + ((long)(fcb * 5 + m) * 4096 + half * 512) * 2;
#pragma unroll
        for (int j = 0; j < 4; j++) {      // 1024 granules, 4/thread
            int idx = j * 256 + tid;
            int ks = idx >> 8, within = idx & 255;
            cp16(saddr(sw + ks * 1024 + within * 4), base + ks * 2048 + within * 4);
        }
        cp_commit();
    };

    for (int jc = 0; jc < 8; ++jc) {
        int s = jc & 1;
        if (jc + 1 < 8) { issue2(jc + 1, s ^ 1); cp_wait1(); }
        else            { cp_wait0(); }
        __syncthreads();
        const uint2* wb = (const uint2*)(pb + s * 4096);

        // prefetch this chunk's x residuals (hidden by MMAs)
        float2 xv[2][4][2];
#pragma unroll
        for (int mt = 0; mt < 2; mt++) {
            long r0 = rowBase + wm2 * 32 + mt * 16 + g;
#pragma unroll
            for (int nt = 0; nt < 4; nt++) {
                int col = jc * 128 + wn2 * 32 + nt * 8 + 2 * t;
                xv[mt][nt][0] = *(const float2*)(x + r0 * FDIM + col);
                xv[mt][nt][1] = *(const float2*)(x + (r0 + 8) * FDIM + col);
            }
        }

        float a2c[2][4][4];
#pragma unroll
        for (int a = 0; a < 2; a++)
#pragma unroll
            for (int b = 0; b < 4; b++)
#pragma unroll
                for (int c = 0; c < 4; c++) a2c[a][b][c] = 0.f;

#pragma unroll
        for (int ks = 0; ks < 4; ks++) {
            int kb = ks * 8;
            uint32_t af[2][4];
#pragma unroll
            for (int mt = 0; mt < 2; mt++) {
                const uint32_t* ap = sH + (wm2 * 32 + mt * 16 + g) * 36;
                af[mt][0] = ap[kb + t];
                af[mt][1] = ap[8 * 36 + kb + t];
                af[mt][2] = ap[kb + t + 4];
                af[mt][3] = ap[8 * 36 + kb + t + 4];
            }
#pragma unroll
            for (int nt = 0; nt < 4; nt++) {
                int c = wn2 * 32 + nt * 8 + g;
                uint2 bb = wb[(ks * 128 + c) * 4 + t];
                mma16(a2c[0][nt], af[0][0], af[0][1], af[0][2], af[0][3], bb.x, bb.y);
                mma16(a2c[1][nt], af[1][0], af[1][1], af[1][2], af[1][3], bb.x, bb.y);
            }
        }

#pragma unroll
        for (int mt = 0; mt < 2; mt++) {
            long r0 = rowBase + wm2 * 32 + mt * 16 + g;
#pragma unroll
            for (int nt = 0; nt < 4; nt++) {
                int col = jc * 128 + wn2 * 32 + nt * 8 + 2 * t;
                float bb0 = B2[m * FDIM + col], bb1 = B2[m * FDIM + col + 1];
                float v0 = a2c[mt][nt][0] + xv[mt][nt][0].x + bb0;
                float v1 = a2c[mt][nt][1] + xv[mt][nt][0].y + bb1;
                float v2 = a2c[mt][nt][2] + xv[mt][nt][1].x + bb0;
                float v3 = a2c[mt][nt][3] + xv[mt][nt][1].y + bb1;
                if (m == 3) {
                    v0 = softplus_f(v0); v1 = softplus_f(v1);
                    v2 = softplus_f(v2); v3 = softplus_f(v3);
                } else if (m == 4) {
                    v0 = sigmoid_f(v0); v1 = sigmoid_f(v1);
                    v2 = sigmoid_f(v2); v3 = sigmoid_f(v3);
                }
                float2 o;
                o.x = v0; o.y = v1;
                *(float2*)(out + ((long)m * N + r0) * FDIM + col) = o;
                o.x = v2; o.y = v3;
                *(float2*)(out + ((long)m * N + r0 + 8) * FDIM + col) = o;
                if (m == 2) {              // q fp16 image for branch 5
                    int cu = col >> 1;
                    g_qh[r0 * 512 + cu] = h2pack(v0, v1);
                    g_qh[(r0 + 8) * 512 + cu] = h2pack(v2, v3);
                }
            }
        }
        __syncthreads();
    }
}

// =====================================================================
// k_mlp5: branch 5 (memory MLP). A = q fp16 image (g_qh);
// epilogue adds x + q (f32 reads). Same structure as k_mlp.
// =====================================================================
__global__ void __launch_bounds__(256, 2)
k_mlp5(const float* __restrict__ x, const float* __restrict__ B1,
       const float* __restrict__ B2, float* __restrict__ out, int N) {
    extern __shared__ uint32_t sm[];
    uint32_t* sH = sm;
    uint32_t* pb = sm + 2304;
    const float* q = out + 2ll * N * FDIM;

    long rowBase = (long)blockIdx.x * 64;
    int tid = threadIdx.x;
    int lane = tid & 31, warp = tid >> 5;
    int g = lane >> 2, t = lane & 3;

    // ---------------- phase 1 ----------------
    int wm = warp >> 1, wn = warp & 1;
    float acc[16];
#pragma unroll
    for (int i = 0; i < 16; i++) acc[i] = 0.f;

    auto issue1 = [&](int it, int s) {
        uint32_t* sx = pb + s * 4352;
        uint32_t* swp = sx + 2304;
        int k0u = it * 32;
#pragma unroll
        for (int j = 0; j < 2; j++) {
            int idx = j * 256 + tid;
            int r = idx >> 3, seg = idx & 7;
            cp16(saddr(sx + r * 36 + seg * 4),
                 g_qh + (rowBase + r) * 512 + k0u + seg * 4);
        }
#pragma unroll
        for (int j = 0; j < 2; j++) {      // W1[5] chunk: 512 granules (contiguous)
            int idx = j * 256 + tid;
            cp16(saddr(swp + idx * 4),
                 (const uint32_t*)g_W1p5h + (long)it * 2048 + idx * 4);
        }
        cp_commit();
    };

    issue1(0, 0); issue1(1, 1);
    for (int it = 0; it < 16; ++it) {
        int s = it % 3;
        if (it + 2 < 16) issue1(it + 2, (it + 2) % 3);
        if (it < 14) cp_wait2(); else if (it == 14) cp_wait1(); else cp_wait0();
        __syncthreads();
        const uint32_t* sx = pb + s * 4352;
        const uint2* wb = (const uint2*)(sx + 2304);
        const uint32_t* ax = sx + (wm * 16 + g) * 36;
#pragma unroll
        for (int ks = 0; ks < 4; ks++) {
            int kb = ks * 8;
            uint32_t a0 = ax[kb + t];
            uint32_t a1 = ax[8 * 36 + kb + t];
            uint32_t a2 = ax[kb + t + 4];
            uint32_t a3 = ax[8 * 36 + kb + t + 4];
#pragma unroll
            for (int nt = 0; nt < 4; nt++) {
                int c = wn * 32 + nt * 8 + g;
                uint2 bb = wb[(ks * 64 + c) * 4 + t];
                mma16(acc + nt * 4, a0, a1, a2, a3, bb.x, bb.y);
            }
        }
        __syncthreads();
    }

    // prefetch phase-2 chunk 0
    {
#pragma unroll
        for (int j = 0; j < 4; j++) {      // 1024 granules (contiguous), 4/thread
            int idx = j * 256 + tid;
            cp16(saddr(pb + idx * 4), (const uint32_t*)g_W2p5h + idx * 4);
        }
        cp_commit();
    }

    // H5 -> smem fp16
    {
        int rl = wm * 16 + g;
#pragma unroll
        for (int nt = 0; nt < 4; nt++) {
            int colh = wn * 32 + nt * 8 + 2 * t;
            float bb0 = B1[320 + colh], bb1 = B1[320 + colh + 1];
            int cu = wn * 16 + nt * 4 + t;
            sH[rl * 36 + cu] = h2pack(fmaxf(acc[nt * 4 + 0] + bb0, 0.f),
                                      fmaxf(acc[nt * 4 + 1] + bb1, 0.f));
            sH[(rl + 8) * 36 + cu] = h2pack(fmaxf(acc[nt * 4 + 2] + bb0, 0.f),
                                            fmaxf(acc[nt * 4 + 3] + bb1, 0.f));
        }
    }

    // ---------------- phase 2 ----------------
    int wm2 = warp >> 2, wn2 = warp & 3;

    auto issue2 = [&](int jc, int s) {
        uint32_t* sw = pb + s * 4096;
#pragma unroll
        for (int j = 0; j < 4; j++) {
            int idx = j * 256 + tid;
            cp16(saddr(sw + idx * 4),
                 (const uint32_t*)g_W2p5h + (long)jc * 4096 + idx * 4);
        }
        cp_commit();
    };

    for (int jc = 0; jc < 8; ++jc) {
        int s = jc & 1;
        if (jc + 1 < 8) { issue2(jc + 1, s ^ 1); cp_wait1(); }
        else            { cp_wait0(); }
        __syncthreads();
        const uint2* wb = (const uint2*)(pb + s * 4096);

        // prefetch x+q residual sums into registers
        float2 xv[2][4][2];
#pragma unroll
        for (int mt = 0; mt < 2; mt++) {
            long r0 = rowBase + wm2 * 32 + mt * 16 + g;
#pragma unroll
            for (int nt = 0; nt < 4; nt++) {
                int col = jc * 128 + wn2 * 32 + nt * 8 + 2 * t;
                float2 a0 = *(const float2*)(x + r0 * FDIM + col);
                float2 b0 = *(const float2*)(q + r0 * FDIM + col);
                float2 a1 = *(const float2*)(x + (r0 + 8) * FDIM + col);
                float2 b1 = *(const float2*)(q + (r0 + 8) * FDIM + col);
                xv[mt][nt][0] = make_float2(a0.x + b0.x, a0.y + b0.y);
                xv[mt][nt][1] = make_float2(a1.x + b1.x, a1.y + b1.y);
            }
        }

        float a2c[2][4][4];
#pragma unroll
        for (int a = 0; a < 2; a++)
#pragma unroll
            for (int b = 0; b < 4; b++)
#pragma unroll
                for (int c = 0; c < 4; c++) a2c[a][b][c] = 0.f;

#pragma unroll
        for (int ks = 0; ks < 4; ks++) {
            int kb = ks * 8;
            uint32_t af[2][4];
#pragma unroll
            for (int mt = 0; mt < 2; mt++) {
                const uint32_t* ap = sH + (wm2 * 32 + mt * 16 + g) * 36;
                af[mt][0] = ap[kb + t];
                af[mt][1] = ap[8 * 36 + kb + t];
                af[mt][2] = ap[kb + t + 4];
                af[mt][3] = ap[8 * 36 + kb + t + 4];
            }
#pragma unroll
            for (int nt = 0; nt < 4; nt++) {
                int c = wn2 * 32 + nt * 8 + g;
                uint2 bb = wb[(ks * 128 + c) * 4 + t];
                mma16(a2c[0][nt], af[0][0], af[0][1], af[0][2], af[0][3], bb.x, bb.y);
                mma16(a2c[1][nt], af[1][0], af[1][1], af[1][2], af[1][3], bb.x, bb.y);
            }
        }

#pragma unroll
        for (int mt = 0; mt < 2; mt++) {
            long r0 = rowBase + wm2 * 32 + mt * 16 + g;
#pragma unroll
            for (int nt = 0; nt < 4; nt++) {
                int col = jc * 128 + wn2 * 32 + nt * 8 + 2 * t;
                float bb0 = B2[5 * FDIM + col], bb1 = B2[5 * FDIM + col + 1];
                float2 o;
                o.x = a2c[mt][nt][0] + xv[mt][nt][0].x + bb0;
                o.y = a2c[mt][nt][1] + xv[mt][nt][0].y + bb1;
                *(float2*)(out + (5ll * N + r0) * FDIM + col) = o;
                o.x = a2c[mt][nt][2] + xv[mt][nt][1].x + bb0;
                o.y = a2c[mt][nt][3] + xv[mt][nt][1].y + bb1;
                *(float2*)(out + (5ll * N + r0 + 8) * FDIM + col) = o;
            }
        }
        __syncthreads();
    }
}

// =====================================================================
extern "C" void kernel_launch(void* const* d_in, const int* in_sizes, int n_in,
                              void* d_out, int out_size) {
    const float* x  = (const float*)d_in[0];
    const float* W1 = (const float*)d_in[1];
    const float* B1 = (const float*)d_in[2];
    const float* W2 = (const float*)d_in[3];
    const float* B2 = (const float*)d_in[4];
    float* out = (float*)d_out;
    int N = in_sizes[0] / FDIM;

    cudaFuncSetAttribute(k_mlp,  cudaFuncAttributeMaxDynamicSharedMemorySize, MLP_SMEM);
    cudaFuncSetAttribute(k_mlp5, cudaFuncAttributeMaxDynamicSharedMemorySize, MLP_SMEM);

    k_xh<<<N * 2, 256>>>(x);
    k_prep<<<768, 256>>>(W1, W2);
    k_mlp<<<(N / 64) * 5, 256, MLP_SMEM>>>(x, B1, B2, out, N);
    k_mlp5<<<N / 64, 256, MLP_SMEM>>>(x, B1, B2, out, N);
}